// round 7
// baseline (speedup 1.0000x reference)
#include <cuda_runtime.h>
#include <math.h>

#define FM_B 2
#define FM_C 256
#define FM_H 50
#define FM_W 50
#define FM_HW (FM_H * FM_W)      // 2500
#define POOL 7
#define NBINS (POOL * POOL)      // 49
#define R_ROIS 256

// Channel-last scratch: [B, H, W, C] = 5.12 MB
__device__ float d_fm_t[FM_B * FM_HW * FM_C];

// ---------------------------------------------------------------------------
// Kernel 1: transpose [B, C, HW] -> [B, HW, C] via 32x32 smem tiles
// ---------------------------------------------------------------------------
__global__ void transpose_kernel(const float* __restrict__ fm) {
    __shared__ float tile[32][33];
    int hw0 = blockIdx.x * 32;
    int c0  = blockIdx.y * 32;
    int b   = blockIdx.z;
    int tx = threadIdx.x;
    int ty = threadIdx.y;

    #pragma unroll
    for (int k = 0; k < 4; ++k) {
        int c  = c0 + ty + k * 8;
        int hw = hw0 + tx;
        if (hw < FM_HW)
            tile[ty + k * 8][tx] = fm[((size_t)b * FM_C + c) * FM_HW + hw];
    }
    __syncthreads();
    #pragma unroll
    for (int k = 0; k < 4; ++k) {
        int hw = hw0 + ty + k * 8;
        int c  = c0 + tx;
        if (hw < FM_HW)
            d_fm_t[((size_t)b * FM_HW + hw) * FM_C + c] = tile[tx][ty + k * 8];
    }
}

// ---------------------------------------------------------------------------
// Kernel 2: block = (roi, ph strip). thread = channel (fully coalesced loads).
// Each thread keeps 7 independent accumulators (one per pw bin) -> MLP ~7
// within each h-row sweep. No smem / syncs in the hot path.
// ---------------------------------------------------------------------------
__global__ void __launch_bounds__(256) roi_pool_strip(
        const float* __restrict__ rois, float* __restrict__ out) {
    int blk = blockIdx.x;
    int r   = blk / POOL;       // roi
    int ph  = blk - r * POOL;   // strip row
    int c   = threadIdx.x;      // channel

    const float* roi = rois + r * 5;
    int b  = (int)roi[0];
    int x1 = (int)rintf(roi[1]);
    int y1 = (int)rintf(roi[2]);
    int x2 = (int)rintf(roi[3]);
    int y2 = (int)rintf(roi[4]);
    int roi_w = max(x2 - x1 + 1, 1);
    int roi_h = max(y2 - y1 + 1, 1);

    // Replicate XLA fast-math: x/7 -> x * fl(1/7)  (0x3E124925)
    const float RCP7 = __uint_as_float(0x3E124925u);
    float bin_w = __fmul_rn((float)roi_w, RCP7);
    float bin_h = __fmul_rn((float)roi_h, RCP7);

    int hs = min(max(y1 + (int)floorf(__fmul_rn((float)ph,       bin_h)), 0), FM_H);
    int he = min(max(y1 + (int)ceilf (__fmul_rn((float)(ph + 1), bin_h)), 0), FM_H);

    int ws[POOL], we[POOL];
    #pragma unroll
    for (int pw = 0; pw < POOL; ++pw) {
        ws[pw] = min(max(x1 + (int)floorf(__fmul_rn((float)pw,       bin_w)), 0), FM_W);
        we[pw] = min(max(x1 + (int)ceilf (__fmul_rn((float)(pw + 1), bin_w)), 0), FM_W);
    }

    const float* base = d_fm_t + ((size_t)b * FM_HW) * FM_C + c;

    float m[POOL];
    #pragma unroll
    for (int pw = 0; pw < POOL; ++pw) m[pw] = -INFINITY;

    for (int h = hs; h < he; ++h) {
        const float* rowp = base + (size_t)(h * FM_W) * FM_C;
        #pragma unroll
        for (int pw = 0; pw < POOL; ++pw) {
            for (int w = ws[pw]; w < we[pw]; ++w) {
                m[pw] = fmaxf(m[pw], __ldg(rowp + (size_t)w * FM_C));
            }
        }
    }

    // 7 contiguous floats per thread: out[(r*256 + c)*49 + ph*7 + pw]
    float* o = out + ((size_t)r * FM_C + c) * NBINS + ph * POOL;
    #pragma unroll
    for (int pw = 0; pw < POOL; ++pw) {
        o[pw] = isinf(m[pw]) ? 0.0f : m[pw];
    }
}

extern "C" void kernel_launch(void* const* d_in, const int* in_sizes, int n_in,
                              void* d_out, int out_size) {
    const float* fm   = (const float*)d_in[0];
    const float* rois = (const float*)d_in[1];
    float* out        = (float*)d_out;

    dim3 tg((FM_HW + 31) / 32, FM_C / 32, FM_B);  // (79, 8, 2)
    transpose_kernel<<<tg, dim3(32, 8)>>>(fm);

    roi_pool_strip<<<R_ROIS * POOL, 256>>>(rois, out);
}

// round 8
// speedup vs baseline: 1.1645x; 1.1645x over previous
#include <cuda_runtime.h>
#include <math.h>
#include <stdint.h>

#define FM_B 2
#define FM_C 256
#define FM_H 50
#define FM_W 50
#define FM_HW (FM_H * FM_W)      // 2500
#define POOL 7
#define NBINS (POOL * POOL)      // 49
#define R_ROIS 256
#define POS_F2 (FM_C / 2)        // 128 float2 per spatial position

// Channel-last scratch: [B, H, W, C] = 5.12 MB
__device__ float d_fm_t[FM_B * FM_HW * FM_C];

// ---------------------------------------------------------------------------
// Kernel 1: transpose [B, C, HW] -> [B, HW, C]
// ---------------------------------------------------------------------------
__global__ void transpose_kernel(const float* __restrict__ fm) {
    __shared__ float tile[32][33];
    int hw0 = blockIdx.x * 32;
    int c0  = blockIdx.y * 32;
    int b   = blockIdx.z;
    int tx = threadIdx.x;
    int ty = threadIdx.y;

    #pragma unroll
    for (int k = 0; k < 4; ++k) {
        int c  = c0 + ty + k * 8;
        int hw = hw0 + tx;
        if (hw < FM_HW)
            tile[ty + k * 8][tx] = fm[((size_t)b * FM_C + c) * FM_HW + hw];
    }
    __syncthreads();
    #pragma unroll
    for (int k = 0; k < 4; ++k) {
        int hw = hw0 + ty + k * 8;
        int c  = c0 + tx;
        if (hw < FM_HW)
            d_fm_t[((size_t)b * FM_HW + hw) * FM_C + c] = tile[tx][ty + k * 8];
    }
}

// ---------------------------------------------------------------------------
// Kernel 2: block = (roi, 64-ch group). Row-pipelined smem: each ROI row is
// cp.async'd once into a double buffer; warp wid<7 reduces column bin pw=wid
// and folds into per-ph accumulators via a membership bitmask.
// ---------------------------------------------------------------------------
__global__ void __launch_bounds__(256) roi_pool_rows(
        const float* __restrict__ rois, float* __restrict__ out) {
    __shared__ float2 s_row[2][FM_W * 32];   // 2 x 12.8 KB row buffers
    __shared__ float  s_res[64 * NBINS];     // 12.25 KB staging
    __shared__ int    s_mask[FM_H];          // per-h: which ph strips contain h

    int r  = blockIdx.x >> 2;
    int cg = blockIdx.x & 3;
    int tid  = threadIdx.x;
    int wid  = tid >> 5;
    int lane = tid & 31;

    // --- uniform ROI decode (all threads; cheap) ---
    const float* roi = rois + r * 5;
    int b  = (int)roi[0];
    int x1 = (int)rintf(roi[1]);
    int y1 = (int)rintf(roi[2]);
    int x2 = (int)rintf(roi[3]);
    int y2 = (int)rintf(roi[4]);
    int roi_w = max(x2 - x1 + 1, 1);
    int roi_h = max(y2 - y1 + 1, 1);
    // Replicate XLA fast-math: x/7 -> x * fl(1/7)  (0x3E124925)
    const float RCP7 = __uint_as_float(0x3E124925u);
    float bin_w = __fmul_rn((float)roi_w, RCP7);
    float bin_h = __fmul_rn((float)roi_h, RCP7);

    int w_lo = min(max(x1, 0), FM_W);  // ws[0]
    int w_hi = min(max(x1 + (int)ceilf(__fmul_rn(7.0f, bin_w)), 0), FM_W);  // we[6]
    int h_lo = min(max(y1, 0), FM_H);  // hs[0]
    int h_hi = min(max(y1 + (int)ceilf(__fmul_rn(7.0f, bin_h)), 0), FM_H);  // he[6]
    int ncols = w_hi - w_lo;

    // This warp's column bin (warp 7 only helps with loads)
    int ws_own = 0, we_own = 0;
    if (wid < POOL) {
        ws_own = min(max(x1 + (int)floorf(__fmul_rn((float)wid,       bin_w)), 0), FM_W);
        we_own = min(max(x1 + (int)ceilf (__fmul_rn((float)(wid + 1), bin_w)), 0), FM_W);
    }
    int cs = ws_own - w_lo, ce = we_own - w_lo;

    // per-h strip membership mask
    if (tid < FM_H) {
        int msk = 0;
        for (int ph = 0; ph < POOL; ++ph) {
            int hsp = min(max(y1 + (int)floorf(__fmul_rn((float)ph,       bin_h)), 0), FM_H);
            int hep = min(max(y1 + (int)ceilf (__fmul_rn((float)(ph + 1), bin_h)), 0), FM_H);
            if (tid >= hsp && tid < hep) msk |= (1 << ph);
        }
        s_mask[tid] = msk;
    }

    // global base for this thread's float2 (2 channels)
    const float2* fmb = reinterpret_cast<const float2*>(
        d_fm_t + (size_t)b * FM_HW * FM_C) + (size_t)cg * 32 + lane;

    uint32_t s_row_u32;
    {
        void* p = (void*)&s_row[0][0];
        asm("{ .reg .u64 t; cvta.to.shared.u64 t, %1; cvt.u32.u64 %0, t; }"
            : "=r"(s_row_u32) : "l"(p));
    }

    float mx[POOL], my[POOL];
    #pragma unroll
    for (int ph = 0; ph < POOL; ++ph) { mx[ph] = -INFINITY; my[ph] = -INFINITY; }

    // --- row pipeline ---
    // issue_row(h, bufsel): warp wid copies positions p = wid, wid+8, ...
    #define ISSUE_ROW(H, BSEL)                                                  \
        do {                                                                    \
            _Pragma("unroll")                                                   \
            for (int k = 0; k < 7; ++k) {                                       \
                int p = wid + k * 8;                                            \
                if (p < ncols) {                                                \
                    uint32_t dst = s_row_u32 +                                  \
                        (uint32_t)(((BSEL) * FM_W * 32 + p * 32 + lane) * 8);   \
                    const float2* src = fmb +                                   \
                        ((size_t)(H) * FM_W + w_lo + p) * POS_F2;               \
                    asm volatile(                                               \
                        "cp.async.ca.shared.global [%0], [%1], 8;"              \
                        :: "r"(dst), "l"(src) : "memory");                      \
                }                                                               \
            }                                                                   \
        } while (0)

    int buf = 0;
    if (h_lo < h_hi) { ISSUE_ROW(h_lo, 0); }
    asm volatile("cp.async.commit_group;" ::: "memory");

    for (int h = h_lo; h < h_hi; ++h) {
        if (h + 1 < h_hi) { ISSUE_ROW(h + 1, (buf ^ 1)); }
        asm volatile("cp.async.commit_group;" ::: "memory");
        asm volatile("cp.async.wait_group 1;" ::: "memory");
        __syncthreads();  // row h visible (+ s_mask on first iter)

        if (wid < POOL) {
            int msk = s_mask[h];
            const float2* rowb = &s_row[buf][0];
            float t0x = -INFINITY, t0y = -INFINITY;
            float t1x = -INFINITY, t1y = -INFINITY;
            int c = cs;
            for (; c + 1 < ce; c += 2) {
                float2 u = rowb[c * 32 + lane];
                float2 v = rowb[(c + 1) * 32 + lane];
                t0x = fmaxf(t0x, u.x); t0y = fmaxf(t0y, u.y);
                t1x = fmaxf(t1x, v.x); t1y = fmaxf(t1y, v.y);
            }
            if (c < ce) {
                float2 u = rowb[c * 32 + lane];
                t0x = fmaxf(t0x, u.x); t0y = fmaxf(t0y, u.y);
            }
            float tx = fmaxf(t0x, t1x);
            float ty = fmaxf(t0y, t1y);
            #pragma unroll
            for (int ph = 0; ph < POOL; ++ph) {
                if (msk & (1 << ph)) {
                    mx[ph] = fmaxf(mx[ph], tx);
                    my[ph] = fmaxf(my[ph], ty);
                }
            }
        }
        __syncthreads();  // consumption done before buffer reuse
        buf ^= 1;
    }

    // --- stage + coalesced writeback ---
    if (wid < POOL) {
        int c0 = lane * 2;
        #pragma unroll
        for (int ph = 0; ph < POOL; ++ph) {
            float vx = mx[ph], vy = my[ph];
            s_res[c0 * NBINS + ph * POOL + wid]       = isinf(vx) ? 0.0f : vx;
            s_res[(c0 + 1) * NBINS + ph * POOL + wid] = isinf(vy) ? 0.0f : vy;
        }
    }
    __syncthreads();

    float* obase = out + (size_t)r * (FM_C * NBINS) + (size_t)cg * 64 * NBINS;
    #pragma unroll
    for (int i = 0; i < 13; ++i) {
        int idx = tid + i * 256;
        if (idx < 64 * NBINS) obase[idx] = s_res[idx];
    }
    #undef ISSUE_ROW
}

extern "C" void kernel_launch(void* const* d_in, const int* in_sizes, int n_in,
                              void* d_out, int out_size) {
    const float* fm   = (const float*)d_in[0];
    const float* rois = (const float*)d_in[1];
    float* out        = (float*)d_out;

    dim3 tg((FM_HW + 31) / 32, FM_C / 32, FM_B);  // (79, 8, 2)
    transpose_kernel<<<tg, dim3(32, 8)>>>(fm);

    roi_pool_rows<<<R_ROIS * 4, 256>>>(rois, out);
}

// round 9
// speedup vs baseline: 2.0658x; 1.7740x over previous
#include <cuda_runtime.h>
#include <math.h>

#define FM_B 2
#define FM_C 256
#define FM_H 50
#define FM_W 50
#define FM_HW (FM_H * FM_W)      // 2500
#define POOL 7
#define NBINS (POOL * POOL)      // 49
#define R_ROIS 256
#define POS_F4 (FM_C / 4)        // 64 float4 per spatial position

// Channel-last scratch: [B, H, W, C] = 5.12 MB
__device__ float d_fm_t[FM_B * FM_HW * FM_C];

// ---------------------------------------------------------------------------
// Kernel 1: transpose [B, C, HW] -> [B, HW, C]
// ---------------------------------------------------------------------------
__global__ void transpose_kernel(const float* __restrict__ fm) {
    __shared__ float tile[32][33];
    int hw0 = blockIdx.x * 32;
    int c0  = blockIdx.y * 32;
    int b   = blockIdx.z;
    int tx = threadIdx.x;
    int ty = threadIdx.y;

    #pragma unroll
    for (int k = 0; k < 4; ++k) {
        int c  = c0 + ty + k * 8;
        int hw = hw0 + tx;
        if (hw < FM_HW)
            tile[ty + k * 8][tx] = fm[((size_t)b * FM_C + c) * FM_HW + hw];
    }
    __syncthreads();
    #pragma unroll
    for (int k = 0; k < 4; ++k) {
        int hw = hw0 + ty + k * 8;
        int c  = c0 + tx;
        if (hw < FM_HW)
            d_fm_t[((size_t)b * FM_HW + hw) * FM_C + c] = tile[tx][ty + k * 8];
    }
}

// ---------------------------------------------------------------------------
// Kernel 2: block = (roi, ph strip, channel half). 128 threads = 4 warps.
// Lane = float4 (4 channels); warp w covers bins pw = w, w+4.
// All loads LDG.128, perfectly coalesced; no syncs in the hot loop.
// ---------------------------------------------------------------------------
__global__ void __launch_bounds__(128) roi_pool_f4(
        const float* __restrict__ rois, float* __restrict__ out) {
    __shared__ float s_res[128 * POOL];   // [c_local][pw], 3.5 KB

    int bid  = blockIdx.x;
    int half = bid & 1;
    int ph   = (bid >> 1) % POOL;
    int r    = bid / (2 * POOL);
    int tid  = threadIdx.x;
    int wid  = tid >> 5;
    int lane = tid & 31;

    // --- uniform ROI decode (all threads) ---
    const float* roi = rois + r * 5;
    int b  = (int)roi[0];
    int x1 = (int)rintf(roi[1]);
    int y1 = (int)rintf(roi[2]);
    int x2 = (int)rintf(roi[3]);
    int y2 = (int)rintf(roi[4]);
    int roi_w = max(x2 - x1 + 1, 1);
    int roi_h = max(y2 - y1 + 1, 1);
    // Replicate XLA fast-math: x/7 -> x * fl(1/7)  (0x3E124925)
    const float RCP7 = __uint_as_float(0x3E124925u);
    float bin_w = __fmul_rn((float)roi_w, RCP7);
    float bin_h = __fmul_rn((float)roi_h, RCP7);

    int hs = min(max(y1 + (int)floorf(__fmul_rn((float)ph,       bin_h)), 0), FM_H);
    int he = min(max(y1 + (int)ceilf (__fmul_rn((float)(ph + 1), bin_h)), 0), FM_H);

    // this thread's float4: channels half*128 + lane*4 .. +3
    const float4* base = reinterpret_cast<const float4*>(d_fm_t)
                       + (size_t)b * FM_HW * POS_F4 + half * 32 + lane;

    // warp handles pw = wid and wid+4 (wid==3 -> only pw=3)
    for (int pw = wid; pw < POOL; pw += 4) {
        int ws = min(max(x1 + (int)floorf(__fmul_rn((float)pw,       bin_w)), 0), FM_W);
        int we = min(max(x1 + (int)ceilf (__fmul_rn((float)(pw + 1), bin_w)), 0), FM_W);

        float4 a0 = make_float4(-INFINITY, -INFINITY, -INFINITY, -INFINITY);
        float4 a1 = a0;

        for (int h = hs; h < he; ++h) {
            const float4* p = base + (size_t)(h * FM_W + ws) * POS_F4;
            int w = ws;
            for (; w + 1 < we; w += 2) {
                float4 v0 = __ldg(p);
                float4 v1 = __ldg(p + POS_F4);
                p += 2 * POS_F4;
                a0.x = fmaxf(a0.x, v0.x); a0.y = fmaxf(a0.y, v0.y);
                a0.z = fmaxf(a0.z, v0.z); a0.w = fmaxf(a0.w, v0.w);
                a1.x = fmaxf(a1.x, v1.x); a1.y = fmaxf(a1.y, v1.y);
                a1.z = fmaxf(a1.z, v1.z); a1.w = fmaxf(a1.w, v1.w);
            }
            if (w < we) {
                float4 v0 = __ldg(p);
                a0.x = fmaxf(a0.x, v0.x); a0.y = fmaxf(a0.y, v0.y);
                a0.z = fmaxf(a0.z, v0.z); a0.w = fmaxf(a0.w, v0.w);
            }
        }
        float m0 = fmaxf(a0.x, a1.x);
        float m1 = fmaxf(a0.y, a1.y);
        float m2 = fmaxf(a0.z, a1.z);
        float m3 = fmaxf(a0.w, a1.w);
        // stage: s_res[c_local * 7 + pw]; lane stride 28 words -> 4-way conflicts, fine
        int c0 = lane * 4;
        s_res[(c0 + 0) * POOL + pw] = (m0 == -INFINITY) ? 0.0f : m0;
        s_res[(c0 + 1) * POOL + pw] = (m1 == -INFINITY) ? 0.0f : m1;
        s_res[(c0 + 2) * POOL + pw] = (m2 == -INFINITY) ? 0.0f : m2;
        s_res[(c0 + 3) * POOL + pw] = (m3 == -INFINITY) ? 0.0f : m3;
    }
    __syncthreads();

    // Writeback: out[(r*256 + half*128 + cl)*49 + ph*7 + pw]
    float* obase = out + ((size_t)r * FM_C + half * 128) * NBINS + ph * POOL;
    #pragma unroll
    for (int k = 0; k < POOL; ++k) {
        int i  = tid + k * 128;      // 0..895
        int cl = i / POOL;
        int pw = i - cl * POOL;
        obase[cl * NBINS + pw] = s_res[i];
    }
}

extern "C" void kernel_launch(void* const* d_in, const int* in_sizes, int n_in,
                              void* d_out, int out_size) {
    const float* fm   = (const float*)d_in[0];
    const float* rois = (const float*)d_in[1];
    float* out        = (float*)d_out;

    dim3 tg((FM_HW + 31) / 32, FM_C / 32, FM_B);  // (79, 8, 2)
    transpose_kernel<<<tg, dim3(32, 8)>>>(fm);

    roi_pool_f4<<<R_ROIS * POOL * 2, 128>>>(rois, out);
}

// round 10
// speedup vs baseline: 2.1605x; 1.0458x over previous
#include <cuda_runtime.h>
#include <math.h>

#define FM_B 2
#define FM_C 256
#define FM_H 50
#define FM_W 50
#define FM_HW (FM_H * FM_W)      // 2500
#define POOL 7
#define NBINS (POOL * POOL)      // 49
#define R_ROIS 256
#define POS_F4 (FM_C / 4)        // 64 float4 per spatial position

// Channel-last scratch: [B, H, W, C] = 5.12 MB
__device__ float d_fm_t[FM_B * FM_HW * FM_C];

// ---------------------------------------------------------------------------
// Kernel 1: transpose [B, C, HW] -> [B, HW, C], float4 both sides.
// block (8,32): load phase tx=hw-float4, ty=c; store phase ty=hw, tx=c-float4.
// tile[c][hw] padded to 33 -> conflict-free both phases.
// ---------------------------------------------------------------------------
__global__ void __launch_bounds__(256) transpose_kernel(const float* __restrict__ fm) {
    __shared__ float tile[32][33];
    int hw0 = blockIdx.x * 32;
    int c0  = blockIdx.y * 32;
    int b   = blockIdx.z;
    int tx = threadIdx.x;   // 0..7
    int ty = threadIdx.y;   // 0..31

    int hw = hw0 + tx * 4;
    const float* src = fm + ((size_t)b * FM_C + c0 + ty) * FM_HW + hw;
    if (hw + 3 < FM_HW) {
        float4 v = *reinterpret_cast<const float4*>(src);
        tile[ty][tx * 4 + 0] = v.x; tile[ty][tx * 4 + 1] = v.y;
        tile[ty][tx * 4 + 2] = v.z; tile[ty][tx * 4 + 3] = v.w;
    } else {
        #pragma unroll
        for (int k = 0; k < 4; ++k)
            if (hw + k < FM_HW) tile[ty][tx * 4 + k] = src[k];
    }
    __syncthreads();

    int hw2 = hw0 + ty;
    if (hw2 < FM_HW) {
        float4 v;
        v.x = tile[tx * 4 + 0][ty]; v.y = tile[tx * 4 + 1][ty];
        v.z = tile[tx * 4 + 2][ty]; v.w = tile[tx * 4 + 3][ty];
        *reinterpret_cast<float4*>(
            d_fm_t + ((size_t)b * FM_HW + hw2) * FM_C + c0 + tx * 4) = v;
    }
}

__device__ __forceinline__ float4 f4max(float4 a, float4 v) {
    a.x = fmaxf(a.x, v.x); a.y = fmaxf(a.y, v.y);
    a.z = fmaxf(a.z, v.z); a.w = fmaxf(a.w, v.w);
    return a;
}

// ---------------------------------------------------------------------------
// Kernel 2: block = (roi, ph strip, channel half). 128 threads = 4 warps.
// Warp fuses its two pw bins (wid, wid+4) AND two h rows per inner iteration:
// up to 8 independent LDG.128 per chain step -> ~2.5x fewer exposed L2 round
// trips than processing bins/rows sequentially.
// ---------------------------------------------------------------------------
__global__ void __launch_bounds__(128) roi_pool_f4(
        const float* __restrict__ rois, float* __restrict__ out) {
    __shared__ float s_res[128 * POOL];   // [c_local][pw]

    int bid  = blockIdx.x;
    int half = bid & 1;
    int ph   = (bid >> 1) % POOL;
    int r    = bid / (2 * POOL);
    int tid  = threadIdx.x;
    int wid  = tid >> 5;
    int lane = tid & 31;

    // --- uniform ROI decode ---
    const float* roi = rois + r * 5;
    int b  = (int)roi[0];
    int x1 = (int)rintf(roi[1]);
    int y1 = (int)rintf(roi[2]);
    int x2 = (int)rintf(roi[3]);
    int y2 = (int)rintf(roi[4]);
    int roi_w = max(x2 - x1 + 1, 1);
    int roi_h = max(y2 - y1 + 1, 1);
    // Replicate XLA fast-math: x/7 -> x * fl(1/7)  (0x3E124925)
    const float RCP7 = __uint_as_float(0x3E124925u);
    float bin_w = __fmul_rn((float)roi_w, RCP7);
    float bin_h = __fmul_rn((float)roi_h, RCP7);

    int hs = min(max(y1 + (int)floorf(__fmul_rn((float)ph,       bin_h)), 0), FM_H);
    int he = min(max(y1 + (int)ceilf (__fmul_rn((float)(ph + 1), bin_h)), 0), FM_H);

    int pwA = wid, pwB = wid + 4;
    int wsA = min(max(x1 + (int)floorf(__fmul_rn((float)pwA,       bin_w)), 0), FM_W);
    int weA = min(max(x1 + (int)ceilf (__fmul_rn((float)(pwA + 1), bin_w)), 0), FM_W);
    int nA = weA - wsA;
    int wsB, weB, nB;
    if (pwB < POOL) {
        wsB = min(max(x1 + (int)floorf(__fmul_rn((float)pwB,       bin_w)), 0), FM_W);
        weB = min(max(x1 + (int)ceilf (__fmul_rn((float)(pwB + 1), bin_w)), 0), FM_W);
        nB = weB - wsB;
    } else {
        wsB = wsA; weB = weA; nB = 0;   // alias B addresses onto A -> L1 dedupe
    }
    int nmax = max(nA, nB);

    const float4* base = reinterpret_cast<const float4*>(d_fm_t)
                       + (size_t)b * FM_HW * POS_F4 + half * 32 + lane;

    const float4 NEG = make_float4(-INFINITY, -INFINITY, -INFINITY, -INFINITY);
    float4 aA0 = NEG, aA1 = NEG, aB0 = NEG, aB1 = NEG;

    for (int h = hs; h < he; h += 2) {
        const float4* r0 = base + (size_t)(h * FM_W) * POS_F4;
        const float4* r1 = base + (size_t)(min(h + 1, FM_H - 1) * FM_W) * POS_F4;
        bool row1 = (h + 1) < he;
        for (int i = 0; i < nmax; i += 2) {
            // clamped-safe addresses (always in-bounds), validity masks the fmax
            int wA0 = max(min(wsA + i,     weA - 1), 0);
            int wA1 = max(min(wsA + i + 1, weA - 1), 0);
            int wB0 = max(min(wsB + i,     weB - 1), 0);
            int wB1 = max(min(wsB + i + 1, weB - 1), 0);
            float4 vA00 = __ldg(r0 + (size_t)wA0 * POS_F4);
            float4 vA01 = __ldg(r0 + (size_t)wA1 * POS_F4);
            float4 vB00 = __ldg(r0 + (size_t)wB0 * POS_F4);
            float4 vB01 = __ldg(r0 + (size_t)wB1 * POS_F4);
            float4 vA10 = __ldg(r1 + (size_t)wA0 * POS_F4);
            float4 vA11 = __ldg(r1 + (size_t)wA1 * POS_F4);
            float4 vB10 = __ldg(r1 + (size_t)wB0 * POS_F4);
            float4 vB11 = __ldg(r1 + (size_t)wB1 * POS_F4);
            bool vA0 = i < nA, vA1 = (i + 1) < nA;
            bool vB0 = i < nB, vB1 = (i + 1) < nB;
            if (vA0)         aA0 = f4max(aA0, vA00);
            if (vA1)         aA0 = f4max(aA0, vA01);
            if (vB0)         aB0 = f4max(aB0, vB00);
            if (vB1)         aB0 = f4max(aB0, vB01);
            if (vA0 && row1) aA1 = f4max(aA1, vA10);
            if (vA1 && row1) aA1 = f4max(aA1, vA11);
            if (vB0 && row1) aB1 = f4max(aB1, vB10);
            if (vB1 && row1) aB1 = f4max(aB1, vB11);
        }
    }
    float4 aA = f4max(aA0, aA1);
    float4 aB = f4max(aB0, aB1);

    int c0 = lane * 4;
    s_res[(c0 + 0) * POOL + pwA] = (aA.x == -INFINITY) ? 0.0f : aA.x;
    s_res[(c0 + 1) * POOL + pwA] = (aA.y == -INFINITY) ? 0.0f : aA.y;
    s_res[(c0 + 2) * POOL + pwA] = (aA.z == -INFINITY) ? 0.0f : aA.z;
    s_res[(c0 + 3) * POOL + pwA] = (aA.w == -INFINITY) ? 0.0f : aA.w;
    if (pwB < POOL) {
        s_res[(c0 + 0) * POOL + pwB] = (aB.x == -INFINITY) ? 0.0f : aB.x;
        s_res[(c0 + 1) * POOL + pwB] = (aB.y == -INFINITY) ? 0.0f : aB.y;
        s_res[(c0 + 2) * POOL + pwB] = (aB.z == -INFINITY) ? 0.0f : aB.z;
        s_res[(c0 + 3) * POOL + pwB] = (aB.w == -INFINITY) ? 0.0f : aB.w;
    }
    __syncthreads();

    // Writeback: out[(r*256 + half*128 + cl)*49 + ph*7 + pw]
    float* obase = out + ((size_t)r * FM_C + half * 128) * NBINS + ph * POOL;
    #pragma unroll
    for (int k = 0; k < POOL; ++k) {
        int i  = tid + k * 128;      // 0..895
        int cl = i / POOL;
        int pw = i - cl * POOL;
        obase[cl * NBINS + pw] = s_res[i];
    }
}

extern "C" void kernel_launch(void* const* d_in, const int* in_sizes, int n_in,
                              void* d_out, int out_size) {
    const float* fm   = (const float*)d_in[0];
    const float* rois = (const float*)d_in[1];
    float* out        = (float*)d_out;

    dim3 tg((FM_HW + 31) / 32, FM_C / 32, FM_B);  // (79, 8, 2)
    transpose_kernel<<<tg, dim3(8, 32)>>>(fm);

    roi_pool_f4<<<R_ROIS * POOL * 2, 128>>>(rois, out);
}

// round 11
// speedup vs baseline: 2.2745x; 1.0528x over previous
#include <cuda_runtime.h>
#include <math.h>

#define FM_B 2
#define FM_C 256
#define FM_H 50
#define FM_W 50
#define FM_HW (FM_H * FM_W)      // 2500
#define POOL 7
#define NBINS (POOL * POOL)      // 49
#define R_ROIS 256
#define POS_F4 (FM_C / 4)        // 64 float4 per spatial position

// Channel-last scratch: [B, H, W, C] = 5.12 MB
__device__ float d_fm_t[FM_B * FM_HW * FM_C];

// ---------------------------------------------------------------------------
// Kernel 1: transpose [B, C, HW] -> [B, HW, C], float4 both sides.
// ---------------------------------------------------------------------------
__global__ void __launch_bounds__(256) transpose_kernel(const float* __restrict__ fm) {
    __shared__ float tile[32][33];
    int hw0 = blockIdx.x * 32;
    int c0  = blockIdx.y * 32;
    int b   = blockIdx.z;
    int tx = threadIdx.x;   // 0..7
    int ty = threadIdx.y;   // 0..31

    int hw = hw0 + tx * 4;
    const float* src = fm + ((size_t)b * FM_C + c0 + ty) * FM_HW + hw;
    if (hw + 3 < FM_HW) {
        float4 v = *reinterpret_cast<const float4*>(src);
        tile[ty][tx * 4 + 0] = v.x; tile[ty][tx * 4 + 1] = v.y;
        tile[ty][tx * 4 + 2] = v.z; tile[ty][tx * 4 + 3] = v.w;
    } else {
        #pragma unroll
        for (int k = 0; k < 4; ++k)
            if (hw + k < FM_HW) tile[ty][tx * 4 + k] = src[k];
    }
    __syncthreads();

    int hw2 = hw0 + ty;
    if (hw2 < FM_HW) {
        float4 v;
        v.x = tile[tx * 4 + 0][ty]; v.y = tile[tx * 4 + 1][ty];
        v.z = tile[tx * 4 + 2][ty]; v.w = tile[tx * 4 + 3][ty];
        *reinterpret_cast<float4*>(
            d_fm_t + ((size_t)b * FM_HW + hw2) * FM_C + c0 + tx * 4) = v;
    }
}

__device__ __forceinline__ float4 f4max(float4 a, float4 v) {
    a.x = fmaxf(a.x, v.x); a.y = fmaxf(a.y, v.y);
    a.z = fmaxf(a.z, v.z); a.w = fmaxf(a.w, v.w);
    return a;
}

// ---------------------------------------------------------------------------
// Kernel 2: block = (roi, ph strip, channel half), 224 threads = 7 warps.
// Warp wid owns bin pw = wid. Lane = float4 of 4 channels (coalesced 512B).
// 2-row x 2-col fusion -> 4 independent LDG.128 per chain step.
// ---------------------------------------------------------------------------
__global__ void __launch_bounds__(224) roi_pool_f4(
        const float* __restrict__ rois, float* __restrict__ out) {
    __shared__ float s_res[128 * POOL];   // [c_local][pw]

    int bid  = blockIdx.x;
    int half = bid & 1;
    int ph   = (bid >> 1) % POOL;
    int r    = bid / (2 * POOL);
    int tid  = threadIdx.x;
    int wid  = tid >> 5;       // 0..6 == pw
    int lane = tid & 31;

    // --- uniform ROI decode ---
    const float* roi = rois + r * 5;
    int b  = (int)roi[0];
    int x1 = (int)rintf(roi[1]);
    int y1 = (int)rintf(roi[2]);
    int x2 = (int)rintf(roi[3]);
    int y2 = (int)rintf(roi[4]);
    int roi_w = max(x2 - x1 + 1, 1);
    int roi_h = max(y2 - y1 + 1, 1);
    // Replicate XLA fast-math: x/7 -> x * fl(1/7)  (0x3E124925)
    const float RCP7 = __uint_as_float(0x3E124925u);
    float bin_w = __fmul_rn((float)roi_w, RCP7);
    float bin_h = __fmul_rn((float)roi_h, RCP7);

    int hs = min(max(y1 + (int)floorf(__fmul_rn((float)ph,       bin_h)), 0), FM_H);
    int he = min(max(y1 + (int)ceilf (__fmul_rn((float)(ph + 1), bin_h)), 0), FM_H);

    int pw = wid;
    int ws = min(max(x1 + (int)floorf(__fmul_rn((float)pw,       bin_w)), 0), FM_W);
    int we = min(max(x1 + (int)ceilf (__fmul_rn((float)(pw + 1), bin_w)), 0), FM_W);
    int n  = we - ws;

    const float4* base = reinterpret_cast<const float4*>(d_fm_t)
                       + (size_t)b * FM_HW * POS_F4 + half * 32 + lane;

    const float4 NEG = make_float4(-INFINITY, -INFINITY, -INFINITY, -INFINITY);
    float4 a0 = NEG, a1 = NEG;

    for (int h = hs; h < he; h += 2) {
        const float4* r0 = base + (size_t)(h * FM_W) * POS_F4;
        const float4* r1 = base + (size_t)(min(h + 1, FM_H - 1) * FM_W) * POS_F4;
        bool row1 = (h + 1) < he;
        for (int i = 0; i < n; i += 2) {
            int w0 = ws + i;
            int w1 = min(ws + i + 1, we - 1);   // odd tail -> duplicate (idempotent)
            float4 v00 = __ldg(r0 + (size_t)w0 * POS_F4);
            float4 v01 = __ldg(r0 + (size_t)w1 * POS_F4);
            float4 v10 = __ldg(r1 + (size_t)w0 * POS_F4);
            float4 v11 = __ldg(r1 + (size_t)w1 * POS_F4);
            a0 = f4max(a0, v00);
            a0 = f4max(a0, v01);
            if (row1) { a1 = f4max(a1, v10); a1 = f4max(a1, v11); }
        }
    }
    float4 a = f4max(a0, a1);

    int c0 = lane * 4;
    s_res[(c0 + 0) * POOL + pw] = (a.x == -INFINITY) ? 0.0f : a.x;
    s_res[(c0 + 1) * POOL + pw] = (a.y == -INFINITY) ? 0.0f : a.y;
    s_res[(c0 + 2) * POOL + pw] = (a.z == -INFINITY) ? 0.0f : a.z;
    s_res[(c0 + 3) * POOL + pw] = (a.w == -INFINITY) ? 0.0f : a.w;
    __syncthreads();

    // Writeback: out[(r*256 + half*128 + cl)*49 + ph*7 + pw]
    float* obase = out + ((size_t)r * FM_C + half * 128) * NBINS + ph * POOL;
    #pragma unroll
    for (int k = 0; k < 4; ++k) {
        int i  = tid + k * 224;      // 0..895
        if (i < 128 * POOL) {
            int cl = i / POOL;
            int pwk = i - cl * POOL;
            obase[cl * NBINS + pwk] = s_res[i];
        }
    }
}

extern "C" void kernel_launch(void* const* d_in, const int* in_sizes, int n_in,
                              void* d_out, int out_size) {
    const float* fm   = (const float*)d_in[0];
    const float* rois = (const float*)d_in[1];
    float* out        = (float*)d_out;

    dim3 tg((FM_HW + 31) / 32, FM_C / 32, FM_B);  // (79, 8, 2)
    transpose_kernel<<<tg, dim3(8, 32)>>>(fm);

    roi_pool_f4<<<R_ROIS * POOL * 2, 224>>>(rois, out);
}